// round 9
// baseline (speedup 1.0000x reference)
#include <cuda_runtime.h>
#include <cstdint>

#define B_     32
#define CIN_   256
#define COUT_  256
#define HW_    56
#define WN_    (COUT_ * CIN_ * 9)
#define BN_EPS 1e-5f

typedef unsigned long long ull;

// Scratch (allocation-free __device__ globals)
__device__ int    g_maxbits;                // static zero-init; atomicMax idempotent
__device__ float2 g_w2[2 * 256 * 9 * 128];  // [coHalf][ci][tap][coLocal] = (wq,wq)
__device__ float  g_scale[COUT_];
__device__ float  g_bias[COUT_];

// ---------------------------------------------------------------------------
__global__ void wmax_kernel(const float* __restrict__ w) {
    float m = 0.0f;
    for (int i = blockIdx.x * blockDim.x + threadIdx.x; i < WN_;
         i += gridDim.x * blockDim.x)
        m = fmaxf(m, fabsf(w[i]));
    #pragma unroll
    for (int o = 16; o > 0; o >>= 1)
        m = fmaxf(m, __shfl_xor_sync(0xFFFFFFFFu, m, o));
    if ((threadIdx.x & 31) == 0)
        atomicMax(&g_maxbits, __float_as_int(m));   // nonneg: int order ok
}

__global__ void wquant_kernel(const float* __restrict__ w) {
    int i = blockIdx.x * blockDim.x + threadIdx.x;
    if (i >= WN_) return;
    float T = tanhf(__int_as_float(g_maxbits));     // max|tanh| = tanh(max|w|)
    float t = tanhf(w[i]);
    float u = t / (2.0f * T) + 0.5f;
    float q = rintf(u * 15.0f) / 15.0f;
    float wq = 2.0f * q - 1.0f;
    int tap = i % 9;
    int ci  = (i / 9) % CIN_;
    int co  = i / (9 * CIN_);
    g_w2[(((co >> 7) * 256 + ci) * 9 + tap) * 128 + (co & 127)] =
        make_float2(wq, wq);
}

__global__ void bnprep_kernel(const float* __restrict__ gamma,
                              const float* __restrict__ beta,
                              const float* __restrict__ mean,
                              const float* __restrict__ var) {
    int c = threadIdx.x;
    float inv = gamma[c] * rsqrtf(var[c] + BN_EPS);
    g_scale[c] = inv;
    g_bias[c]  = beta[c] - mean[c] * inv;
}

// ---------------------------------------------------------------------------
#define FFMA2(d, a, b) \
    asm("fma.rn.f32x2 %0, %1, %2, %0;" : "+l"(d) : "l"(a), "l"(b))

static __device__ __forceinline__ void cp16(uint32_t dst, const void* src) {
    asm volatile("cp.async.cg.shared.global [%0], [%1], 16;"
                 :: "r"(dst), "l"(src));
}
#define CP_COMMIT() asm volatile("cp.async.commit_group;")
#define CP_WAIT0()  asm volatile("cp.async.wait_group 0;" ::: "memory")

// SMEM: W double buf [8ci][9tap][128co]f2, X double buf [8ci][5j][58s]f2, BN.
#define WD_SZ   73728
#define X2_SZ   23040
#define X2_CI   2880
#define X2_ROW  576
#define X2_OFF  (2 * WD_SZ)            // 147456
#define BN_OFF  (X2_OFF + 2 * X2_SZ)   // 193536
#define SMEM_TOT (BN_OFF + 1024)

extern __shared__ char smem[];
static __device__ __forceinline__ int coff(int s) { return (s + (s >> 2)) * 8; }

// ---------------------------------------------------------------------------
// Fused conv(3x3,pad1)+BN+PACT, packed-f32x2 FFMA2 direct conv.
// CTA: 512 thr (16 warps -> 4/SMSP), image n, 4-row band, 128-co half.
// Thread: rp=tid>>8 (1 row-pair), cg=(tid>>3)&31 (4 co), colg=tid&7 (7 cols)
//   -> 28 f32x2 accumulators (~120 regs, no spills).
// ---------------------------------------------------------------------------
__global__ void __launch_bounds__(512, 1)
conv_f32x2_kernel(const float* __restrict__ x,
                  const float* __restrict__ alpha,
                  float* __restrict__ out) {
    const int tid  = threadIdx.x;
    const int colg = tid & 7;
    const int cg   = (tid >> 3) & 31;
    const int rp   = tid >> 8;           // 0..1
    const int c0   = colg * 7;
    const int co0  = cg * 4;
    const int y0   = blockIdx.x * 4;
    const int coH  = blockIdx.y;
    const int n    = blockIdx.z;

    const uint32_t sb = (uint32_t)__cvta_generic_to_shared(smem);
    float* sScale = (float*)(smem + BN_OFF);
    float* sBias  = (float*)(smem + BN_OFF + 512);
    if (tid < 128) {
        sScale[tid] = g_scale[coH * 128 + tid];
        sBias[tid]  = g_bias[coH * 128 + tid];
    }

    int xoff[9];
    #pragma unroll
    for (int m = 0; m < 9; ++m) xoff[m] = coff(c0 + m);

    ull acc[7][4];
    #pragma unroll
    for (int cc = 0; cc < 7; ++cc)
        #pragma unroll
        for (int j8 = 0; j8 < 4; ++j8) acc[cc][j8] = 0ull;

    const float2* wsrc = g_w2 + (size_t)coH * 256 * 9 * 128;
    const float*  xn   = x + (size_t)n * CIN_ * 3136;

    // ---- prologue: stage chunk 0 (X direct, W cp.async) ----
    for (int i = tid; i < 2320; i += 512) {
        int s = i % 58, j = (i / 58) % 5, ci = i / 290;
        int col = s - 1, r0 = y0 - 1 + j;
        const float* xp = xn + (size_t)ci * 3136 + col;
        bool cok = (col >= 0) & (col < HW_);
        float v0 = (cok && r0 >= 0 && r0 < HW_)         ? xp[r0 * 56]       : 0.0f;
        float v1 = (cok && r0 + 1 >= 0 && r0 + 1 < HW_) ? xp[(r0 + 1) * 56] : 0.0f;
        *(float2*)(smem + X2_OFF + ci * X2_CI + j * X2_ROW + coff(s)) =
            make_float2(v0, v1);
    }
    {
        const char* src = (const char*)wsrc;
        for (int i = tid; i < 4608; i += 512) cp16(sb + i * 16, src + i * 16);
        CP_COMMIT();
    }

    for (int ch = 0; ch < 32; ++ch) {
        const int buf = ch & 1;
        CP_WAIT0();
        __syncthreads();

        // prefetch next chunk: W async now, X LDGs into regs (STS after compute)
        float v0s[5], v1s[5];
        if (ch < 31) {
            const char* src = (const char*)(wsrc + (size_t)(ch + 1) * 8 * 9 * 128);
            uint32_t dst = sb + (buf ^ 1) * WD_SZ;
            for (int i = tid; i < 4608; i += 512) cp16(dst + i * 16, src + i * 16);
            CP_COMMIT();
            const float* xc = xn + (size_t)(ch + 1) * 8 * 3136;
            #pragma unroll
            for (int k = 0; k < 5; ++k) {
                int i = tid + k * 512;
                if (i < 2320) {
                    int s = i % 58, j = (i / 58) % 5, ci = i / 290;
                    int col = s - 1, r0 = y0 - 1 + j;
                    const float* xp = xc + (size_t)ci * 3136 + col;
                    bool cok = (col >= 0) & (col < HW_);
                    v0s[k] = (cok && r0 >= 0 && r0 < HW_)         ? xp[r0 * 56]       : 0.0f;
                    v1s[k] = (cok && r0 + 1 >= 0 && r0 + 1 < HW_) ? xp[(r0 + 1) * 56] : 0.0f;
                }
            }
        }

        // ---- compute chunk ch ----
        const char* xb = smem + X2_OFF + buf * X2_SZ;
        const char* wb = smem + buf * WD_SZ;
        for (int ci = 0; ci < 8; ++ci) {
            const char* xc = xb + ci * X2_CI + (2 * rp) * X2_ROW;
            const char* wc = wb + ci * 9216;
            #pragma unroll
            for (int ky = 0; ky < 3; ++ky) {
                ull xa[9];
                #pragma unroll
                for (int m = 0; m < 9; ++m)
                    xa[m] = *(const ull*)(xc + ky * X2_ROW + xoff[m]);
                #pragma unroll
                for (int kx = 0; kx < 3; ++kx) {
                    ull wv[4];
                    const char* wt = wc + (ky * 3 + kx) * 1024 + co0 * 8;
                    {
                        ulonglong2 u0 = *(const ulonglong2*)(wt);
                        ulonglong2 u1 = *(const ulonglong2*)(wt + 16);
                        wv[0] = u0.x; wv[1] = u0.y; wv[2] = u1.x; wv[3] = u1.y;
                    }
                    #pragma unroll
                    for (int cc = 0; cc < 7; ++cc)
                        #pragma unroll
                        for (int j8 = 0; j8 < 4; ++j8)
                            FFMA2(acc[cc][j8], xa[cc + kx], wv[j8]);
                }
            }
        }

        // store prefetched X pairs (visible after next iteration's barrier)
        if (ch < 31) {
            char* xd = smem + X2_OFF + (buf ^ 1) * X2_SZ;
            #pragma unroll
            for (int k = 0; k < 5; ++k) {
                int i = tid + k * 512;
                if (i < 2320) {
                    int s = i % 58, j = (i / 58) % 5, ci = i / 290;
                    *(float2*)(xd + ci * X2_CI + j * X2_ROW + coff(s)) =
                        make_float2(v0s[k], v1s[k]);
                }
            }
        }
    }

    // ---- epilogue: BN + PACT -> smem [co][228] -> coalesced float4 STG ----
    __syncthreads();                     // compute done; W/X smem reusable
    const float aV   = __ldg(alpha);
    const float r15a = 15.0f / aV;
    const float a15  = aV / 15.0f;
    float* sT = (float*)smem;            // 128 co x 228 floats = 116736 B
    #pragma unroll
    for (int j8 = 0; j8 < 4; ++j8) {
        const float sc = sScale[co0 + j8], bi = sBias[co0 + j8];
        #pragma unroll
        for (int cc = 0; cc < 7; ++cc) {
            float lo, hi;
            asm("mov.b64 {%0, %1}, %2;" : "=f"(lo), "=f"(hi) : "l"(acc[cc][j8]));
            float v0 = fminf(fmaxf(lo * sc + bi, 0.0f), aV);
            float v1 = fminf(fmaxf(hi * sc + bi, 0.0f), aV);
            v0 = rintf(v0 * r15a) * a15;
            v1 = rintf(v1 * r15a) * a15;
            sT[(co0 + j8) * 228 + (2 * rp)     * 56 + c0 + cc] = v0;
            sT[(co0 + j8) * 228 + (2 * rp + 1) * 56 + c0 + cc] = v1;
        }
    }
    __syncthreads();
    float* ob = out + (size_t)(n * COUT_ + coH * 128) * 3136 + y0 * 56;
    #pragma unroll
    for (int k = 0; k < 14; ++k) {
        int idx = tid + k * 512;          // 0..7167
        int co = idx / 56, q = idx - co * 56;
        float4 v4 = *(float4*)(sT + co * 228 + q * 4);
        *(float4*)(ob + (size_t)co * 3136 + q * 4) = v4;
    }
}

// ---------------------------------------------------------------------------
extern "C" void kernel_launch(void* const* d_in, const int* in_sizes, int n_in,
                              void* d_out, int out_size) {
    const float* x      = (const float*)d_in[0];
    const float* weight = (const float*)d_in[1];
    const float* gamma  = (const float*)d_in[2];
    const float* beta   = (const float*)d_in[3];
    const float* rmean  = (const float*)d_in[4];
    const float* rvar   = (const float*)d_in[5];
    const float* alpha  = (const float*)d_in[6];
    float* out = (float*)d_out;

    wmax_kernel<<<576, 256>>>(weight);
    wquant_kernel<<<(WN_ + 255) / 256, 256>>>(weight);
    bnprep_kernel<<<1, 256>>>(gamma, beta, rmean, rvar);

    cudaFuncSetAttribute(conv_f32x2_kernel,
                         cudaFuncAttributeMaxDynamicSharedMemorySize, SMEM_TOT);
    dim3 grid(14, 2, B_);
    conv_f32x2_kernel<<<grid, 512, SMEM_TOT>>>(x, alpha, out);
}

// round 10
// speedup vs baseline: 1.0769x; 1.0769x over previous
#include <cuda_runtime.h>
#include <cstdint>

#define B_     32
#define CIN_   256
#define COUT_  256
#define HW_    56
#define WN_    (COUT_ * CIN_ * 9)
#define BN_EPS 1e-5f

typedef unsigned long long ull;

// Scratch (allocation-free __device__ globals)
__device__ int    g_maxbits;                // static zero-init; atomicMax idempotent
__device__ float2 g_w2[2 * 256 * 9 * 128];  // [coHalf][ci][tap][coLocal] = (wq,wq)
__device__ float  g_scale[COUT_];
__device__ float  g_bias[COUT_];

// ---------------------------------------------------------------------------
__global__ void wmax_kernel(const float* __restrict__ w) {
    float m = 0.0f;
    for (int i = blockIdx.x * blockDim.x + threadIdx.x; i < WN_;
         i += gridDim.x * blockDim.x)
        m = fmaxf(m, fabsf(w[i]));
    #pragma unroll
    for (int o = 16; o > 0; o >>= 1)
        m = fmaxf(m, __shfl_xor_sync(0xFFFFFFFFu, m, o));
    if ((threadIdx.x & 31) == 0)
        atomicMax(&g_maxbits, __float_as_int(m));   // nonneg: int order ok
}

__global__ void wquant_kernel(const float* __restrict__ w) {
    int i = blockIdx.x * blockDim.x + threadIdx.x;
    if (i >= WN_) return;
    float T = tanhf(__int_as_float(g_maxbits));     // max|tanh| = tanh(max|w|)
    float t = tanhf(w[i]);
    float u = t / (2.0f * T) + 0.5f;
    float q = rintf(u * 15.0f) / 15.0f;
    float wq = 2.0f * q - 1.0f;
    int tap = i % 9;
    int ci  = (i / 9) % CIN_;
    int co  = i / (9 * CIN_);
    g_w2[(((co >> 7) * 256 + ci) * 9 + tap) * 128 + (co & 127)] =
        make_float2(wq, wq);
}

__global__ void bnprep_kernel(const float* __restrict__ gamma,
                              const float* __restrict__ beta,
                              const float* __restrict__ mean,
                              const float* __restrict__ var) {
    int c = threadIdx.x;
    float inv = gamma[c] * rsqrtf(var[c] + BN_EPS);
    g_scale[c] = inv;
    g_bias[c]  = beta[c] - mean[c] * inv;
}

// ---------------------------------------------------------------------------
#define FFMA2(d, a, b) \
    asm("fma.rn.f32x2 %0, %1, %2, %0;" : "+l"(d) : "l"(a), "l"(b))

static __device__ __forceinline__ void cp16(uint32_t dst, const void* src) {
    asm volatile("cp.async.cg.shared.global [%0], [%1], 16;"
                 :: "r"(dst), "l"(src));
}
#define CP_COMMIT() asm volatile("cp.async.commit_group;")
#define CP_WAIT0()  asm volatile("cp.async.wait_group 0;" ::: "memory")

// SMEM per CTA (<=113KB so 2 CTAs/SM):
//   W double buf [4ci][9tap][128co] float2 : 36864 * 2 = 73728
//   X double buf [4ci][3j][58s] float2 pad : 6912  * 2 = 13824
//   BN tables                               : 1024
#define WD_SZ   36864
#define X2_SZ   6912
#define X2_CI   1728
#define X2_ROW  576
#define X2_OFF  (2 * WD_SZ)            // 73728
#define BN_OFF  (X2_OFF + 2 * X2_SZ)   // 87552
#define SMEM_TOT (BN_OFF + 1024)       // 88576

extern __shared__ char smem[];
static __device__ __forceinline__ int coff(int s) { return (s + (s >> 2)) * 8; }

// ---------------------------------------------------------------------------
// Fused conv(3x3,pad1)+BN+PACT, packed-f32x2 FFMA2 direct conv.
// CTA: 256 thr, 2 CTAs/SM (16 warps/SM). Image n, 2-row band (1 row-pair),
// 128-co half. Thread: colg=tid&7 (7 cols), cg=tid>>3 (4 co) -> 28 f32x2 accs.
// ---------------------------------------------------------------------------
__global__ void __launch_bounds__(256, 2)
conv_f32x2_kernel(const float* __restrict__ x,
                  const float* __restrict__ alpha,
                  float* __restrict__ out) {
    const int tid  = threadIdx.x;
    const int colg = tid & 7;
    const int cg   = tid >> 3;           // 0..31
    const int c0   = colg * 7;
    const int co0  = cg * 4;
    const int y0   = blockIdx.x * 2;
    const int coH  = blockIdx.y;
    const int n    = blockIdx.z;

    const uint32_t sb = (uint32_t)__cvta_generic_to_shared(smem);
    float* sScale = (float*)(smem + BN_OFF);
    float* sBias  = (float*)(smem + BN_OFF + 512);
    if (tid < 128) {
        sScale[tid] = g_scale[coH * 128 + tid];
        sBias[tid]  = g_bias[coH * 128 + tid];
    }

    int xoff[9];
    #pragma unroll
    for (int m = 0; m < 9; ++m) xoff[m] = coff(c0 + m);

    ull acc[7][4];
    #pragma unroll
    for (int cc = 0; cc < 7; ++cc)
        #pragma unroll
        for (int j8 = 0; j8 < 4; ++j8) acc[cc][j8] = 0ull;

    const float2* wsrc = g_w2 + (size_t)coH * 256 * 9 * 128;
    const float*  xn   = x + (size_t)n * CIN_ * 3136;

    // ---- prologue: stage chunk 0 (X direct, W cp.async) ----
    for (int i = tid; i < 696; i += 256) {
        int s = i % 58, j = (i / 58) % 3, ci = i / 174;
        int col = s - 1, r0 = y0 - 1 + j;
        const float* xp = xn + (size_t)ci * 3136 + col;
        bool cok = (col >= 0) & (col < HW_);
        float v0 = (cok && r0 >= 0 && r0 < HW_)         ? xp[r0 * 56]       : 0.0f;
        float v1 = (cok && r0 + 1 >= 0 && r0 + 1 < HW_) ? xp[(r0 + 1) * 56] : 0.0f;
        *(float2*)(smem + X2_OFF + ci * X2_CI + j * X2_ROW + coff(s)) =
            make_float2(v0, v1);
    }
    {
        const char* src = (const char*)wsrc;
        for (int i = tid; i < 2304; i += 256) cp16(sb + i * 16, src + i * 16);
        CP_COMMIT();
    }

    for (int ch = 0; ch < 64; ++ch) {
        const int buf = ch & 1;
        CP_WAIT0();
        __syncthreads();

        // prefetch next chunk: W async now, X LDGs into regs (STS after compute)
        float v0s[3], v1s[3];
        if (ch < 63) {
            const char* src = (const char*)(wsrc + (size_t)(ch + 1) * 4 * 9 * 128);
            uint32_t dst = sb + (buf ^ 1) * WD_SZ;
            for (int i = tid; i < 2304; i += 256) cp16(dst + i * 16, src + i * 16);
            CP_COMMIT();
            const float* xc = xn + (size_t)(ch + 1) * 4 * 3136;
            #pragma unroll
            for (int k = 0; k < 3; ++k) {
                int i = tid + k * 256;
                if (i < 696) {
                    int s = i % 58, j = (i / 58) % 3, ci = i / 174;
                    int col = s - 1, r0 = y0 - 1 + j;
                    const float* xp = xc + (size_t)ci * 3136 + col;
                    bool cok = (col >= 0) & (col < HW_);
                    v0s[k] = (cok && r0 >= 0 && r0 < HW_)         ? xp[r0 * 56]       : 0.0f;
                    v1s[k] = (cok && r0 + 1 >= 0 && r0 + 1 < HW_) ? xp[(r0 + 1) * 56] : 0.0f;
                }
            }
        }

        // ---- compute chunk ch (4 ci) ----
        const char* xb = smem + X2_OFF + buf * X2_SZ;
        const char* wb = smem + buf * WD_SZ;
        #pragma unroll
        for (int ci = 0; ci < 4; ++ci) {
            const char* xc = xb + ci * X2_CI;
            const char* wc = wb + ci * 9216;
            #pragma unroll
            for (int ky = 0; ky < 3; ++ky) {
                ull xa[9];
                #pragma unroll
                for (int m = 0; m < 9; ++m)
                    xa[m] = *(const ull*)(xc + ky * X2_ROW + xoff[m]);
                #pragma unroll
                for (int kx = 0; kx < 3; ++kx) {
                    ull wv[4];
                    const char* wt = wc + (ky * 3 + kx) * 1024 + co0 * 8;
                    {
                        ulonglong2 u0 = *(const ulonglong2*)(wt);
                        ulonglong2 u1 = *(const ulonglong2*)(wt + 16);
                        wv[0] = u0.x; wv[1] = u0.y; wv[2] = u1.x; wv[3] = u1.y;
                    }
                    #pragma unroll
                    for (int cc = 0; cc < 7; ++cc)
                        #pragma unroll
                        for (int j8 = 0; j8 < 4; ++j8)
                            FFMA2(acc[cc][j8], xa[cc + kx], wv[j8]);
                }
            }
        }

        // store prefetched X pairs (visible after next iteration's barrier)
        if (ch < 63) {
            char* xd = smem + X2_OFF + (buf ^ 1) * X2_SZ;
            #pragma unroll
            for (int k = 0; k < 3; ++k) {
                int i = tid + k * 256;
                if (i < 696) {
                    int s = i % 58, j = (i / 58) % 3, ci = i / 174;
                    *(float2*)(xd + ci * X2_CI + j * X2_ROW + coff(s)) =
                        make_float2(v0s[k], v1s[k]);
                }
            }
        }
    }

    // ---- epilogue: BN + PACT -> smem [co][116] -> coalesced float4 STG ----
    __syncthreads();                     // compute done; W/X smem reusable
    const float aV   = __ldg(alpha);
    const float r15a = 15.0f / aV;
    const float a15  = aV / 15.0f;
    float* sT = (float*)smem;            // 128 co x 116 floats = 59392 B
    #pragma unroll
    for (int j8 = 0; j8 < 4; ++j8) {
        const float sc = sScale[co0 + j8], bi = sBias[co0 + j8];
        #pragma unroll
        for (int cc = 0; cc < 7; ++cc) {
            float lo, hi;
            asm("mov.b64 {%0, %1}, %2;" : "=f"(lo), "=f"(hi) : "l"(acc[cc][j8]));
            float v0 = fminf(fmaxf(lo * sc + bi, 0.0f), aV);
            float v1 = fminf(fmaxf(hi * sc + bi, 0.0f), aV);
            v0 = rintf(v0 * r15a) * a15;
            v1 = rintf(v1 * r15a) * a15;
            sT[(co0 + j8) * 116 + c0 + cc]      = v0;
            sT[(co0 + j8) * 116 + 56 + c0 + cc] = v1;
        }
    }
    __syncthreads();
    float* ob = out + (size_t)(n * COUT_ + coH * 128) * 3136 + y0 * 56;
    #pragma unroll
    for (int k = 0; k < 14; ++k) {
        int idx = tid + k * 256;          // 0..3583  (128co x 112 floats /4)
        int co = idx / 28, q = idx - co * 28;
        float4 v4 = *(float4*)(sT + co * 116 + q * 4);
        *(float4*)(ob + (size_t)co * 3136 + q * 4) = v4;
    }
}

// ---------------------------------------------------------------------------
extern "C" void kernel_launch(void* const* d_in, const int* in_sizes, int n_in,
                              void* d_out, int out_size) {
    const float* x      = (const float*)d_in[0];
    const float* weight = (const float*)d_in[1];
    const float* gamma  = (const float*)d_in[2];
    const float* beta   = (const float*)d_in[3];
    const float* rmean  = (const float*)d_in[4];
    const float* rvar   = (const float*)d_in[5];
    const float* alpha  = (const float*)d_in[6];
    float* out = (float*)d_out;

    wmax_kernel<<<576, 256>>>(weight);
    wquant_kernel<<<(WN_ + 255) / 256, 256>>>(weight);
    bnprep_kernel<<<1, 256>>>(gamma, beta, rmean, rvar);

    cudaFuncSetAttribute(conv_f32x2_kernel,
                         cudaFuncAttributeMaxDynamicSharedMemorySize, SMEM_TOT);
    dim3 grid(28, 2, B_);
    conv_f32x2_kernel<<<grid, 256, SMEM_TOT>>>(x, alpha, out);
}